// round 2
// baseline (speedup 1.0000x reference)
#include <cuda_runtime.h>
#include <cstddef>

// Problem constants (match reference)
#define ND   40000
#define NP   20000
#define RREL 4
#define E_DDI 200000
#define E_PDI 200000
#define FD   128
#define FP   256
#define FO   128

// Degree buffer layout (all stored as rsqrt(clip(deg,1)) after finalize)
#define OFF_OUT_DDI 0              // [4][ND]
#define OFF_IN_DDI  (4*ND)         // [4][ND]
#define OFF_OUT_PDI (8*ND)         // [NP]
#define OFF_IN_PDI  (8*ND + NP)    // [ND]
#define DEG_TOTAL   (8*ND + NP + ND)

// Scratch (static device globals: no allocation allowed)
__device__ float g_agg[(size_t)ND * 512];   // stacked per-relation aggregation [ND][4*128]
__device__ float g_h1[(size_t)ND * FO];
__device__ float g_h2[(size_t)ND * FO];
__device__ float g_hp[(size_t)NP * FO];
__device__ float g_deg[DEG_TOTAL];

// ---------------------------------------------------------------------------
// Vector atomic add (sm_90+): 4 floats per red op
// ---------------------------------------------------------------------------
__device__ __forceinline__ void red_add_v4(float4* addr, float4 v) {
    asm volatile("red.global.add.v4.f32 [%0], {%1, %2, %3, %4};"
                 :: "l"(addr), "f"(v.x), "f"(v.y), "f"(v.z), "f"(v.w)
                 : "memory");
}

// ---------------------------------------------------------------------------
// Degree computation
// ---------------------------------------------------------------------------
__global__ void count_ddi_kernel(const int* __restrict__ src,
                                 const int* __restrict__ dst) {
    int r = blockIdx.y;
    int e = blockIdx.x * blockDim.x + threadIdx.x;
    if (e >= E_DDI) return;
    int s = src[r * E_DDI + e];
    int d = dst[r * E_DDI + e];
    atomicAdd(&g_deg[OFF_OUT_DDI + r * ND + s], 1.0f);
    atomicAdd(&g_deg[OFF_IN_DDI  + r * ND + d], 1.0f);
}

__global__ void count_pdi_kernel(const int* __restrict__ src,
                                 const int* __restrict__ dst) {
    int e = blockIdx.x * blockDim.x + threadIdx.x;
    if (e >= E_PDI) return;
    atomicAdd(&g_deg[OFF_OUT_PDI + src[e]], 1.0f);
    atomicAdd(&g_deg[OFF_IN_PDI  + dst[e]], 1.0f);
}

__global__ void finalize_deg_kernel() {
    int i = blockIdx.x * blockDim.x + threadIdx.x;
    if (i >= DEG_TOTAL) return;
    float v = g_deg[i];
    g_deg[i] = rsqrtf(v < 1.0f ? 1.0f : v);
}

// ---------------------------------------------------------------------------
// DDI edge scatter: one warp per edge; fully-normalized contribution
//   g_agg[dst][r*128 + f] += x[src][f] * rn_out[r][src] * rn_in[r][dst]
// ---------------------------------------------------------------------------
__global__ void scatter_ddi_kernel(const float* __restrict__ x,
                                   const int* __restrict__ src,
                                   const int* __restrict__ dst) {
    int r = blockIdx.y;
    int e = blockIdx.x * (blockDim.x >> 5) + (threadIdx.x >> 5);
    if (e >= E_DDI) return;
    int lane = threadIdx.x & 31;
    int s = __ldg(src + (size_t)r * E_DDI + e);
    int d = __ldg(dst + (size_t)r * E_DDI + e);
    float c = __ldg(g_deg + OFF_OUT_DDI + r * ND + s) *
              __ldg(g_deg + OFF_IN_DDI  + r * ND + d);
    float4 v = __ldg((const float4*)x + (size_t)s * 32 + lane);
    v.x *= c; v.y *= c; v.z *= c; v.w *= c;
    red_add_v4((float4*)(g_agg + (size_t)d * 512 + r * 128) + lane, v);
}

// PDI scatter: h1[dst] += hp[src] * rn_in_pdi[dst]  (src norm folded into GEMM)
__global__ void scatter_pdi_kernel(const int* __restrict__ src,
                                   const int* __restrict__ dst) {
    int e = blockIdx.x * (blockDim.x >> 5) + (threadIdx.x >> 5);
    if (e >= E_PDI) return;
    int lane = threadIdx.x & 31;
    int s = __ldg(src + e);
    int d = __ldg(dst + e);
    float c = __ldg(g_deg + OFF_IN_PDI + d);
    float4 v = __ldg((const float4*)g_hp + (size_t)s * 32 + lane);
    v.x *= c; v.y *= c; v.z *= c; v.w *= c;
    red_add_v4((float4*)(g_h1 + (size_t)d * 128) + lane, v);
}

// ---------------------------------------------------------------------------
// SGEMM: C[M,128] = (accum ? C : 0) + A[M,K] @ B[K,128] + sum_r bias[r] (+bias2)
// optional per-row scale on A (folds rsqrt(out-degree) for PDI), optional relu.
// BM=128, BN=128, BK=16, 256 threads, 8x8 per thread.
// ---------------------------------------------------------------------------
#define BM 128
#define BN 128
#define BK 16

__global__ __launch_bounds__(256)
void gemm128_kernel(const float* __restrict__ A, const float* __restrict__ B,
                    float* __restrict__ C, int M, int K,
                    const float* __restrict__ bias, int bias_rows,
                    const float* __restrict__ bias2,
                    const float* __restrict__ row_scale,
                    int accum, int do_relu) {
    __shared__ float As[BK][BM + 4];
    __shared__ float Bs[BK][BN];

    const int tid = threadIdx.x;
    const int tx = tid & 15;        // output col group
    const int ty = tid >> 4;        // output row group
    const int a_r = tid >> 2;       // 0..63
    const int a_c = (tid & 3) << 2; // 0,4,8,12
    const int b_r = tid >> 5;       // 0..7
    const int b_c = (tid & 31) << 2;
    const int row0 = blockIdx.x * BM;

    float acc[8][8];
    #pragma unroll
    for (int i = 0; i < 8; i++)
        #pragma unroll
        for (int j = 0; j < 8; j++) acc[i][j] = 0.0f;

    for (int k0 = 0; k0 < K; k0 += BK) {
        // Load A tile (transposed into smem), with optional row scaling
        #pragma unroll
        for (int h = 0; h < 2; h++) {
            int r = a_r + h * 64;
            int gm = row0 + r;
            float4 v = make_float4(0.f, 0.f, 0.f, 0.f);
            if (gm < M) {
                v = __ldg((const float4*)(A + (size_t)gm * K + k0 + a_c));
                if (row_scale) {
                    float sc = __ldg(row_scale + gm);
                    v.x *= sc; v.y *= sc; v.z *= sc; v.w *= sc;
                }
            }
            As[a_c + 0][r] = v.x;
            As[a_c + 1][r] = v.y;
            As[a_c + 2][r] = v.z;
            As[a_c + 3][r] = v.w;
        }
        // Load B tile
        #pragma unroll
        for (int h = 0; h < 2; h++) {
            int r = b_r + h * 8;
            *(float4*)&Bs[r][b_c] =
                __ldg((const float4*)(B + (size_t)(k0 + r) * BN + b_c));
        }
        __syncthreads();

        #pragma unroll
        for (int k = 0; k < BK; k++) {
            float4 a0 = *(const float4*)&As[k][ty * 8];
            float4 a1 = *(const float4*)&As[k][ty * 8 + 4];
            float4 b0 = *(const float4*)&Bs[k][tx * 8];
            float4 b1 = *(const float4*)&Bs[k][tx * 8 + 4];
            float ra[8] = {a0.x, a0.y, a0.z, a0.w, a1.x, a1.y, a1.z, a1.w};
            float rb[8] = {b0.x, b0.y, b0.z, b0.w, b1.x, b1.y, b1.z, b1.w};
            #pragma unroll
            for (int i = 0; i < 8; i++)
                #pragma unroll
                for (int j = 0; j < 8; j++)
                    acc[i][j] = fmaf(ra[i], rb[j], acc[i][j]);
        }
        __syncthreads();
    }

    // Bias (sum over bias_rows relation biases + optional extra)
    float bsum[8];
    #pragma unroll
    for (int j = 0; j < 8; j++) {
        int col = tx * 8 + j;
        float b = 0.0f;
        for (int rr = 0; rr < bias_rows; rr++) b += __ldg(bias + rr * BN + col);
        if (bias2) b += __ldg(bias2 + col);
        bsum[j] = b;
    }

    #pragma unroll
    for (int i = 0; i < 8; i++) {
        int gm = row0 + ty * 8 + i;
        if (gm >= M) continue;
        float* cp = C + (size_t)gm * BN + tx * 8;
        #pragma unroll
        for (int jj = 0; jj < 2; jj++) {
            float4 o;
            float4 old = make_float4(0.f, 0.f, 0.f, 0.f);
            if (accum) old = *(float4*)(cp + jj * 4);
            o.x = old.x + acc[i][jj * 4 + 0] + bsum[jj * 4 + 0];
            o.y = old.y + acc[i][jj * 4 + 1] + bsum[jj * 4 + 1];
            o.z = old.z + acc[i][jj * 4 + 2] + bsum[jj * 4 + 2];
            o.w = old.w + acc[i][jj * 4 + 3] + bsum[jj * 4 + 3];
            if (do_relu) {
                o.x = fmaxf(o.x, 0.f); o.y = fmaxf(o.y, 0.f);
                o.z = fmaxf(o.z, 0.f); o.w = fmaxf(o.w, 0.f);
            }
            *(float4*)(cp + jj * 4) = o;
        }
    }
}

// ---------------------------------------------------------------------------
// Launch
// ---------------------------------------------------------------------------
extern "C" void kernel_launch(void* const* d_in, const int* in_sizes, int n_in,
                              void* d_out, int out_size) {
    const float* x_d    = (const float*)d_in[0];
    const float* x_p    = (const float*)d_in[1];
    const float* W1     = (const float*)d_in[2];   // [4,128,128] == [512,128]
    const float* b1     = (const float*)d_in[3];   // [4,128]
    const float* W1_pdi = (const float*)d_in[4];   // [256,128]
    const float* b1_pdi = (const float*)d_in[5];   // [128]
    // d_in[6], d_in[7]: W1_ppi / b1_ppi -- dead code, unused
    const float* W2     = (const float*)d_in[8];
    const float* b2     = (const float*)d_in[9];
    const float* W3     = (const float*)d_in[10];
    const float* b3     = (const float*)d_in[11];
    const int* ddi_src  = (const int*)d_in[12];
    const int* ddi_dst  = (const int*)d_in[13];
    const int* pdi_src  = (const int*)d_in[14];
    const int* pdi_dst  = (const int*)d_in[15];
    // d_in[16], d_in[17]: ppi edges -- dead code, unused
    float* out = (float*)d_out;

    float *agg, *h1, *h2, *hp, *deg;
    cudaGetSymbolAddress((void**)&agg, g_agg);
    cudaGetSymbolAddress((void**)&h1, g_h1);
    cudaGetSymbolAddress((void**)&h2, g_h2);
    cudaGetSymbolAddress((void**)&hp, g_hp);
    cudaGetSymbolAddress((void**)&deg, g_deg);

    const float* rn_out_pdi = deg + OFF_OUT_PDI;

    const int GEMM_BLOCKS_D = (ND + BM - 1) / BM;   // 313
    const int GEMM_BLOCKS_P = (NP + BM - 1) / BM;   // 157
    const int WARPS_PER_BLK = 8;
    const dim3 SCAT_DDI((E_DDI + WARPS_PER_BLK - 1) / WARPS_PER_BLK, RREL);
    const dim3 CNT_DDI((E_DDI + 255) / 256, RREL);

    // --- degrees (recomputed every call: deterministic, inputs on device) ---
    cudaMemsetAsync(deg, 0, (size_t)DEG_TOTAL * sizeof(float));
    count_ddi_kernel<<<CNT_DDI, 256>>>(ddi_src, ddi_dst);
    count_pdi_kernel<<<(E_PDI + 255) / 256, 256>>>(pdi_src, pdi_dst);
    finalize_deg_kernel<<<(DEG_TOTAL + 255) / 256, 256>>>();

    // --- Layer 1 ---
    cudaMemsetAsync(agg, 0, (size_t)ND * 512 * sizeof(float));
    cudaMemsetAsync(h1, 0, (size_t)ND * FO * sizeof(float));
    scatter_ddi_kernel<<<SCAT_DDI, 256>>>(x_d, ddi_src, ddi_dst);
    // PDI branch: hp = (x_p * rsqrt(dout_pdi)) @ W1_pdi
    gemm128_kernel<<<GEMM_BLOCKS_P, 256>>>(x_p, W1_pdi, hp, NP, FP,
                                           nullptr, 0, nullptr, rn_out_pdi, 0, 0);
    scatter_pdi_kernel<<<(E_PDI + WARPS_PER_BLK - 1) / WARPS_PER_BLK, 256>>>(pdi_src, pdi_dst);
    // h1 = relu(h1_pdi + agg @ W1 + sum_r b1[r] + b1_pdi)
    gemm128_kernel<<<GEMM_BLOCKS_D, 256>>>(agg, W1, h1, ND, 512,
                                           b1, RREL, b1_pdi, nullptr, 1, 1);

    // --- Layer 2 ---
    cudaMemsetAsync(agg, 0, (size_t)ND * 512 * sizeof(float));
    scatter_ddi_kernel<<<SCAT_DDI, 256>>>(h1, ddi_src, ddi_dst);
    gemm128_kernel<<<GEMM_BLOCKS_D, 256>>>(agg, W2, h2, ND, 512,
                                           b2, RREL, nullptr, nullptr, 0, 1);

    // --- Layer 3 ---
    cudaMemsetAsync(agg, 0, (size_t)ND * 512 * sizeof(float));
    scatter_ddi_kernel<<<SCAT_DDI, 256>>>(h2, ddi_src, ddi_dst);
    gemm128_kernel<<<GEMM_BLOCKS_D, 256>>>(agg, W3, out, ND, 512,
                                           b3, RREL, nullptr, nullptr, 0, 0);
}

// round 3
// speedup vs baseline: 1.1849x; 1.1849x over previous
#include <cuda_runtime.h>
#include <cstddef>

// Problem constants (match reference)
#define ND   40000
#define NP   20000
#define RREL 4
#define E_DDI 200000
#define E_PDI 200000
#define FD   128
#define FP   256
#define FO   128

// Degree buffer layout (all stored as rsqrt(clip(deg,1)) after finalize)
#define OFF_OUT_DDI 0              // [4][ND]
#define OFF_IN_DDI  (4*ND)         // [4][ND]
#define OFF_OUT_PDI (8*ND)         // [NP]
#define OFF_IN_PDI  (8*ND + NP)    // [ND]
#define DEG_TOTAL   (8*ND + NP + ND)

// Scratch (static device globals: no allocation allowed)
__device__ float g_agg[(size_t)ND * 512];   // stacked per-relation aggregation [ND][4*128]
__device__ float g_h1[(size_t)ND * FO];
__device__ float g_h2[(size_t)ND * FO];
__device__ float g_hp[(size_t)NP * FO];
__device__ float g_deg[DEG_TOTAL];

// ---------------------------------------------------------------------------
// Vector atomic add (sm_90+): 4 floats per red op
// ---------------------------------------------------------------------------
__device__ __forceinline__ void red_add_v4(float4* addr, float4 v) {
    asm volatile("red.global.add.v4.f32 [%0], {%1, %2, %3, %4};"
                 :: "l"(addr), "f"(v.x), "f"(v.y), "f"(v.z), "f"(v.w)
                 : "memory");
}

// ---------------------------------------------------------------------------
// Degree computation
// ---------------------------------------------------------------------------
__global__ void count_ddi_kernel(const int* __restrict__ src,
                                 const int* __restrict__ dst) {
    int r = blockIdx.y;
    int e = blockIdx.x * blockDim.x + threadIdx.x;
    if (e >= E_DDI) return;
    int s = src[r * E_DDI + e];
    int d = dst[r * E_DDI + e];
    atomicAdd(&g_deg[OFF_OUT_DDI + r * ND + s], 1.0f);
    atomicAdd(&g_deg[OFF_IN_DDI  + r * ND + d], 1.0f);
}

__global__ void count_pdi_kernel(const int* __restrict__ src,
                                 const int* __restrict__ dst) {
    int e = blockIdx.x * blockDim.x + threadIdx.x;
    if (e >= E_PDI) return;
    atomicAdd(&g_deg[OFF_OUT_PDI + src[e]], 1.0f);
    atomicAdd(&g_deg[OFF_IN_PDI  + dst[e]], 1.0f);
}

__global__ void finalize_deg_kernel() {
    int i = blockIdx.x * blockDim.x + threadIdx.x;
    if (i >= DEG_TOTAL) return;
    float v = g_deg[i];
    g_deg[i] = rsqrtf(v < 1.0f ? 1.0f : v);
}

// ---------------------------------------------------------------------------
// DDI edge scatter v2: 32 edges per warp per round.
// Phase 1: each lane loads ITS OWN edge's (src, dst, coef) -- coalesced.
// Phase 2: 32 rounds; round j broadcasts edge j's regs via shfl, all 32
//          lanes gather x[src] (float4/lane) and red.add into agg[dst].
// 32 independent LDG+RED chains in flight per warp -> high MLP.
//   g_agg[dst][r*128 + f] += x[src][f] * rn_out[r][src] * rn_in[r][dst]
// ---------------------------------------------------------------------------
__global__ void scatter_ddi_kernel(const float* __restrict__ x,
                                   const int* __restrict__ src,
                                   const int* __restrict__ dst) {
    const int r = blockIdx.y;
    const int lane = threadIdx.x & 31;
    const int warp = blockIdx.x * (blockDim.x >> 5) + (threadIdx.x >> 5);
    const int e0 = warp * 32;
    if (e0 >= E_DDI) return;
    const int n = (E_DDI - e0 < 32) ? (E_DDI - e0) : 32;

    int soff = 0, doff = 0;
    float c = 0.0f;
    if (lane < n) {
        int e = e0 + lane;
        int s = __ldg(src + (size_t)r * E_DDI + e);
        int d = __ldg(dst + (size_t)r * E_DDI + e);
        c = __ldg(g_deg + OFF_OUT_DDI + r * ND + s) *
            __ldg(g_deg + OFF_IN_DDI  + r * ND + d);
        soff = s * 32;            // x row in float4 units (128 floats)
        doff = d * 128 + r * 32;  // agg row in float4 units (512 floats)
    }

    const float4* __restrict__ xv = (const float4*)x;
    float4* aggv = (float4*)g_agg;

    if (n == 32) {
        #pragma unroll 4
        for (int j = 0; j < 32; j++) {
            int sj   = __shfl_sync(0xffffffffu, soff, j);
            int dj   = __shfl_sync(0xffffffffu, doff, j);
            float cj = __shfl_sync(0xffffffffu, c, j);
            float4 v = __ldg(xv + sj + lane);
            v.x *= cj; v.y *= cj; v.z *= cj; v.w *= cj;
            red_add_v4(aggv + dj + lane, v);
        }
    } else {
        for (int j = 0; j < n; j++) {
            int sj   = __shfl_sync(0xffffffffu, soff, j);
            int dj   = __shfl_sync(0xffffffffu, doff, j);
            float cj = __shfl_sync(0xffffffffu, c, j);
            float4 v = __ldg(xv + sj + lane);
            v.x *= cj; v.y *= cj; v.z *= cj; v.w *= cj;
            red_add_v4(aggv + dj + lane, v);
        }
    }
}

// PDI scatter v2: same staging scheme.
// h1[dst] += hp[src] * rn_in_pdi[dst]  (src norm folded into GEMM)
__global__ void scatter_pdi_kernel(const int* __restrict__ src,
                                   const int* __restrict__ dst) {
    const int lane = threadIdx.x & 31;
    const int warp = blockIdx.x * (blockDim.x >> 5) + (threadIdx.x >> 5);
    const int e0 = warp * 32;
    if (e0 >= E_PDI) return;
    const int n = (E_PDI - e0 < 32) ? (E_PDI - e0) : 32;

    int soff = 0, doff = 0;
    float c = 0.0f;
    if (lane < n) {
        int e = e0 + lane;
        int s = __ldg(src + e);
        int d = __ldg(dst + e);
        c = __ldg(g_deg + OFF_IN_PDI + d);
        soff = s * 32;
        doff = d * 32;
    }

    const float4* __restrict__ hpv = (const float4*)g_hp;
    float4* h1v = (float4*)g_h1;

    #pragma unroll 4
    for (int j = 0; j < 32; j++) {
        if (j >= n) break;
        int sj   = __shfl_sync(0xffffffffu, soff, j);
        int dj   = __shfl_sync(0xffffffffu, doff, j);
        float cj = __shfl_sync(0xffffffffu, c, j);
        float4 v = __ldg(hpv + sj + lane);
        v.x *= cj; v.y *= cj; v.z *= cj; v.w *= cj;
        red_add_v4(h1v + dj + lane, v);
    }
}

// ---------------------------------------------------------------------------
// SGEMM v2: register-staged double-buffered pipeline.
// C[M,128] = (accum ? C : 0) + A[M,K] @ B[K,128] + sum_r bias[r] (+bias2)
// optional per-row scale on A, optional relu.
// BM=128, BN=128, BK=16, 256 threads, 8x8 per thread, 2-stage smem.
// ---------------------------------------------------------------------------
#define BM 128
#define BN 128
#define BK 16

__global__ __launch_bounds__(256, 2)
void gemm128_kernel(const float* __restrict__ A, const float* __restrict__ B,
                    float* __restrict__ C, int M, int K,
                    const float* __restrict__ bias, int bias_rows,
                    const float* __restrict__ bias2,
                    const float* __restrict__ row_scale,
                    int accum, int do_relu) {
    __shared__ float As[2][BK][BM + 4];
    __shared__ float Bs[2][BK][BN];

    const int tid = threadIdx.x;
    const int tx = tid & 15;        // output col group
    const int ty = tid >> 4;        // output row group
    const int a_r = tid >> 2;       // 0..63
    const int a_c = (tid & 3) << 2; // 0,4,8,12
    const int b_r = tid >> 5;       // 0..7
    const int b_c = (tid & 31) << 2;
    const int row0 = blockIdx.x * BM;

    // row-scale factors for the two A rows this thread loads
    float rs0 = 1.0f, rs1 = 1.0f;
    const int gm0 = row0 + a_r;
    const int gm1 = row0 + a_r + 64;
    if (row_scale) {
        if (gm0 < M) rs0 = __ldg(row_scale + gm0);
        if (gm1 < M) rs1 = __ldg(row_scale + gm1);
    }

    float acc[8][8];
    #pragma unroll
    for (int i = 0; i < 8; i++)
        #pragma unroll
        for (int j = 0; j < 8; j++) acc[i][j] = 0.0f;

    float4 pa0, pa1, pb0, pb1;   // register staging for next tile

    // --- load tile 0 into regs ---
    {
        pa0 = make_float4(0.f,0.f,0.f,0.f);
        pa1 = make_float4(0.f,0.f,0.f,0.f);
        if (gm0 < M) pa0 = __ldg((const float4*)(A + (size_t)gm0 * K + a_c));
        if (gm1 < M) pa1 = __ldg((const float4*)(A + (size_t)gm1 * K + a_c));
        pb0 = __ldg((const float4*)(B + (size_t)b_r * BN + b_c));
        pb1 = __ldg((const float4*)(B + (size_t)(b_r + 8) * BN + b_c));
    }
    // --- store tile 0 to smem buf 0 ---
    {
        As[0][a_c + 0][a_r] = pa0.x * rs0;
        As[0][a_c + 1][a_r] = pa0.y * rs0;
        As[0][a_c + 2][a_r] = pa0.z * rs0;
        As[0][a_c + 3][a_r] = pa0.w * rs0;
        As[0][a_c + 0][a_r + 64] = pa1.x * rs1;
        As[0][a_c + 1][a_r + 64] = pa1.y * rs1;
        As[0][a_c + 2][a_r + 64] = pa1.z * rs1;
        As[0][a_c + 3][a_r + 64] = pa1.w * rs1;
        *(float4*)&Bs[0][b_r][b_c]     = pb0;
        *(float4*)&Bs[0][b_r + 8][b_c] = pb1;
    }
    __syncthreads();

    const int ntiles = K / BK;
    int buf = 0;

    for (int t = 0; t < ntiles; t++) {
        // prefetch next tile into registers (overlaps with compute below)
        const int k0n = (t + 1) * BK;
        if (t + 1 < ntiles) {
            pa0 = make_float4(0.f,0.f,0.f,0.f);
            pa1 = make_float4(0.f,0.f,0.f,0.f);
            if (gm0 < M) pa0 = __ldg((const float4*)(A + (size_t)gm0 * K + k0n + a_c));
            if (gm1 < M) pa1 = __ldg((const float4*)(A + (size_t)gm1 * K + k0n + a_c));
            pb0 = __ldg((const float4*)(B + (size_t)(k0n + b_r) * BN + b_c));
            pb1 = __ldg((const float4*)(B + (size_t)(k0n + b_r + 8) * BN + b_c));
        }

        // compute on current buffer
        #pragma unroll
        for (int k = 0; k < BK; k++) {
            float4 a0 = *(const float4*)&As[buf][k][ty * 8];
            float4 a1 = *(const float4*)&As[buf][k][ty * 8 + 4];
            float4 b0 = *(const float4*)&Bs[buf][k][tx * 8];
            float4 b1 = *(const float4*)&Bs[buf][k][tx * 8 + 4];
            float ra[8] = {a0.x, a0.y, a0.z, a0.w, a1.x, a1.y, a1.z, a1.w};
            float rb[8] = {b0.x, b0.y, b0.z, b0.w, b1.x, b1.y, b1.z, b1.w};
            #pragma unroll
            for (int i = 0; i < 8; i++)
                #pragma unroll
                for (int j = 0; j < 8; j++)
                    acc[i][j] = fmaf(ra[i], rb[j], acc[i][j]);
        }

        // stage next tile into the other buffer
        if (t + 1 < ntiles) {
            int nb = buf ^ 1;
            As[nb][a_c + 0][a_r] = pa0.x * rs0;
            As[nb][a_c + 1][a_r] = pa0.y * rs0;
            As[nb][a_c + 2][a_r] = pa0.z * rs0;
            As[nb][a_c + 3][a_r] = pa0.w * rs0;
            As[nb][a_c + 0][a_r + 64] = pa1.x * rs1;
            As[nb][a_c + 1][a_r + 64] = pa1.y * rs1;
            As[nb][a_c + 2][a_r + 64] = pa1.z * rs1;
            As[nb][a_c + 3][a_r + 64] = pa1.w * rs1;
            *(float4*)&Bs[nb][b_r][b_c]     = pb0;
            *(float4*)&Bs[nb][b_r + 8][b_c] = pb1;
            __syncthreads();
            buf = nb;
        }
    }

    // Bias (sum over bias_rows relation biases + optional extra)
    float bsum[8];
    #pragma unroll
    for (int j = 0; j < 8; j++) {
        int col = tx * 8 + j;
        float b = 0.0f;
        for (int rr = 0; rr < bias_rows; rr++) b += __ldg(bias + rr * BN + col);
        if (bias2) b += __ldg(bias2 + col);
        bsum[j] = b;
    }

    #pragma unroll
    for (int i = 0; i < 8; i++) {
        int gm = row0 + ty * 8 + i;
        if (gm >= M) continue;
        float* cp = C + (size_t)gm * BN + tx * 8;
        #pragma unroll
        for (int jj = 0; jj < 2; jj++) {
            float4 o;
            float4 old = make_float4(0.f, 0.f, 0.f, 0.f);
            if (accum) old = *(float4*)(cp + jj * 4);
            o.x = old.x + acc[i][jj * 4 + 0] + bsum[jj * 4 + 0];
            o.y = old.y + acc[i][jj * 4 + 1] + bsum[jj * 4 + 1];
            o.z = old.z + acc[i][jj * 4 + 2] + bsum[jj * 4 + 2];
            o.w = old.w + acc[i][jj * 4 + 3] + bsum[jj * 4 + 3];
            if (do_relu) {
                o.x = fmaxf(o.x, 0.f); o.y = fmaxf(o.y, 0.f);
                o.z = fmaxf(o.z, 0.f); o.w = fmaxf(o.w, 0.f);
            }
            *(float4*)(cp + jj * 4) = o;
        }
    }
}

// ---------------------------------------------------------------------------
// Launch
// ---------------------------------------------------------------------------
extern "C" void kernel_launch(void* const* d_in, const int* in_sizes, int n_in,
                              void* d_out, int out_size) {
    const float* x_d    = (const float*)d_in[0];
    const float* x_p    = (const float*)d_in[1];
    const float* W1     = (const float*)d_in[2];   // [4,128,128] == [512,128]
    const float* b1     = (const float*)d_in[3];   // [4,128]
    const float* W1_pdi = (const float*)d_in[4];   // [256,128]
    const float* b1_pdi = (const float*)d_in[5];   // [128]
    // d_in[6], d_in[7]: W1_ppi / b1_ppi -- dead code, unused
    const float* W2     = (const float*)d_in[8];
    const float* b2     = (const float*)d_in[9];
    const float* W3     = (const float*)d_in[10];
    const float* b3     = (const float*)d_in[11];
    const int* ddi_src  = (const int*)d_in[12];
    const int* ddi_dst  = (const int*)d_in[13];
    const int* pdi_src  = (const int*)d_in[14];
    const int* pdi_dst  = (const int*)d_in[15];
    // d_in[16], d_in[17]: ppi edges -- dead code, unused
    float* out = (float*)d_out;

    float *agg, *h1, *h2, *hp, *deg;
    cudaGetSymbolAddress((void**)&agg, g_agg);
    cudaGetSymbolAddress((void**)&h1, g_h1);
    cudaGetSymbolAddress((void**)&h2, g_h2);
    cudaGetSymbolAddress((void**)&hp, g_hp);
    cudaGetSymbolAddress((void**)&deg, g_deg);

    const float* rn_out_pdi = deg + OFF_OUT_PDI;

    const int GEMM_BLOCKS_D = (ND + BM - 1) / BM;   // 313
    const int GEMM_BLOCKS_P = (NP + BM - 1) / BM;   // 157
    // scatter v2: 32 edges per warp, 8 warps (256 edges) per block
    const int SCAT_DDI_BLKS = (E_DDI + 255) / 256;  // 782
    const int SCAT_PDI_BLKS = (E_PDI + 255) / 256;
    const dim3 SCAT_DDI(SCAT_DDI_BLKS, RREL);
    const dim3 CNT_DDI((E_DDI + 255) / 256, RREL);

    // --- degrees (recomputed every call: deterministic, inputs on device) ---
    cudaMemsetAsync(deg, 0, (size_t)DEG_TOTAL * sizeof(float));
    count_ddi_kernel<<<CNT_DDI, 256>>>(ddi_src, ddi_dst);
    count_pdi_kernel<<<(E_PDI + 255) / 256, 256>>>(pdi_src, pdi_dst);
    finalize_deg_kernel<<<(DEG_TOTAL + 255) / 256, 256>>>();

    // --- Layer 1 ---
    cudaMemsetAsync(agg, 0, (size_t)ND * 512 * sizeof(float));
    cudaMemsetAsync(h1, 0, (size_t)ND * FO * sizeof(float));
    scatter_ddi_kernel<<<SCAT_DDI, 256>>>(x_d, ddi_src, ddi_dst);
    // PDI branch: hp = (x_p * rsqrt(dout_pdi)) @ W1_pdi
    gemm128_kernel<<<GEMM_BLOCKS_P, 256>>>(x_p, W1_pdi, hp, NP, FP,
                                           nullptr, 0, nullptr, rn_out_pdi, 0, 0);
    scatter_pdi_kernel<<<SCAT_PDI_BLKS, 256>>>(pdi_src, pdi_dst);
    // h1 = relu(h1_pdi + agg @ W1 + sum_r b1[r] + b1_pdi)
    gemm128_kernel<<<GEMM_BLOCKS_D, 256>>>(agg, W1, h1, ND, 512,
                                           b1, RREL, b1_pdi, nullptr, 1, 1);

    // --- Layer 2 ---
    cudaMemsetAsync(agg, 0, (size_t)ND * 512 * sizeof(float));
    scatter_ddi_kernel<<<SCAT_DDI, 256>>>(h1, ddi_src, ddi_dst);
    gemm128_kernel<<<GEMM_BLOCKS_D, 256>>>(agg, W2, h2, ND, 512,
                                           b2, RREL, nullptr, nullptr, 0, 1);

    // --- Layer 3 ---
    cudaMemsetAsync(agg, 0, (size_t)ND * 512 * sizeof(float));
    scatter_ddi_kernel<<<SCAT_DDI, 256>>>(h2, ddi_src, ddi_dst);
    gemm128_kernel<<<GEMM_BLOCKS_D, 256>>>(agg, W3, out, ND, 512,
                                           b3, RREL, nullptr, nullptr, 0, 0);
}

// round 5
// speedup vs baseline: 1.3622x; 1.1497x over previous
#include <cuda_runtime.h>
#include <cstddef>
#include <cstdint>

// Problem constants (match reference)
#define ND   40000
#define NP   20000
#define RREL 4
#define E_DDI 200000
#define E_PDI 200000
#define FD   128
#define FP   256
#define FO   128

// Degree buffer layout (all stored as rsqrt(clip(deg,1)) after finalize)
#define OFF_OUT_DDI 0              // [4][ND]
#define OFF_IN_DDI  (4*ND)         // [4][ND]
#define OFF_OUT_PDI (8*ND)         // [NP]
#define OFF_IN_PDI  (8*ND + NP)    // [ND]
#define DEG_TOTAL   (8*ND + NP + ND)

// Scratch (static device globals: no allocation allowed)
__device__ float g_y[(size_t)RREL * ND * FO];  // per-relation transformed feats
__device__ float g_h1[(size_t)ND * FO];
__device__ float g_h2[(size_t)ND * FO];
__device__ float g_hp[(size_t)NP * FO];
__device__ float g_deg[DEG_TOTAL];

// ---------------------------------------------------------------------------
// Vector atomic add (sm_90+): 4 floats per red op
// ---------------------------------------------------------------------------
__device__ __forceinline__ void red_add_v4(float4* addr, float4 v) {
    asm volatile("red.global.add.v4.f32 [%0], {%1, %2, %3, %4};"
                 :: "l"(addr), "f"(v.x), "f"(v.y), "f"(v.z), "f"(v.w)
                 : "memory");
}

// tf32 split helpers (Markidis 3xTF32)
__device__ __forceinline__ uint32_t f2tf32(float v) {
    uint32_t r;
    asm("cvt.rna.tf32.f32 %0, %1;" : "=r"(r) : "f"(v));
    return r;
}
__device__ __forceinline__ void split_tf32(float v, uint32_t& hi, uint32_t& lo) {
    hi = f2tf32(v);
    lo = f2tf32(v - __uint_as_float(hi));
}

__device__ __forceinline__ void mma_tf32(float* c, const uint32_t* a,
                                         uint32_t b0, uint32_t b1) {
    asm volatile(
        "mma.sync.aligned.m16n8k8.row.col.f32.tf32.tf32.f32 "
        "{%0,%1,%2,%3}, {%4,%5,%6,%7}, {%8,%9}, {%0,%1,%2,%3};"
        : "+f"(c[0]), "+f"(c[1]), "+f"(c[2]), "+f"(c[3])
        : "r"(a[0]), "r"(a[1]), "r"(a[2]), "r"(a[3]), "r"(b0), "r"(b1));
}

// ---------------------------------------------------------------------------
// Degree computation
// ---------------------------------------------------------------------------
__global__ void count_ddi_kernel(const int* __restrict__ src,
                                 const int* __restrict__ dst) {
    int r = blockIdx.y;
    int e = blockIdx.x * blockDim.x + threadIdx.x;
    if (e >= E_DDI) return;
    int s = src[r * E_DDI + e];
    int d = dst[r * E_DDI + e];
    atomicAdd(&g_deg[OFF_OUT_DDI + r * ND + s], 1.0f);
    atomicAdd(&g_deg[OFF_IN_DDI  + r * ND + d], 1.0f);
}

__global__ void count_pdi_kernel(const int* __restrict__ src,
                                 const int* __restrict__ dst) {
    int e = blockIdx.x * blockDim.x + threadIdx.x;
    if (e >= E_PDI) return;
    atomicAdd(&g_deg[OFF_OUT_PDI + src[e]], 1.0f);
    atomicAdd(&g_deg[OFF_IN_PDI  + dst[e]], 1.0f);
}

__global__ void finalize_deg_kernel() {
    int i = blockIdx.x * blockDim.x + threadIdx.x;
    if (i >= DEG_TOTAL) return;
    float v = g_deg[i];
    g_deg[i] = rsqrtf(v < 1.0f ? 1.0f : v);
}

// ---------------------------------------------------------------------------
// Bias broadcast init: h[i][j] = sum_r bias[r][j] (+ bias2[j])
// ---------------------------------------------------------------------------
__global__ void bias_init_kernel(float* __restrict__ h,
                                 const float* __restrict__ bias, int bias_rows,
                                 const float* __restrict__ bias2, int M) {
    int idx = blockIdx.x * blockDim.x + threadIdx.x;   // one float4 each
    if (idx >= M * 32) return;
    int c4 = (idx & 31) * 4;
    float4 b = make_float4(0.f, 0.f, 0.f, 0.f);
    for (int rr = 0; rr < bias_rows; rr++) {
        b.x += __ldg(bias + rr * FO + c4 + 0);
        b.y += __ldg(bias + rr * FO + c4 + 1);
        b.z += __ldg(bias + rr * FO + c4 + 2);
        b.w += __ldg(bias + rr * FO + c4 + 3);
    }
    if (bias2) {
        b.x += __ldg(bias2 + c4 + 0);
        b.y += __ldg(bias2 + c4 + 1);
        b.z += __ldg(bias2 + c4 + 2);
        b.w += __ldg(bias2 + c4 + 3);
    }
    ((float4*)h)[idx] = b;
}

// ---------------------------------------------------------------------------
// Per-relation 3xTF32 tensor GEMM:
//   Y[r][M,128] = act(A[M,128]) @ W[r][128,128]
// Grid (ceil(M/128), RREL). Whole A-tile + W_r resident in dynamic smem.
// 256 threads = 8 warps in 4x2 (warp: 32 rows x 64 cols), mma m16n8k8.
// ---------------------------------------------------------------------------
#define AS_STRIDE 132
#define BS_STRIDE 136
#define GEMM_SMEM ((128 * AS_STRIDE + 128 * BS_STRIDE) * 4)

__global__ __launch_bounds__(256, 1)
void gemm_tf32_rel_kernel(const float* __restrict__ A,
                          const float* __restrict__ W,   // [RREL,128,128]
                          float* __restrict__ Y,          // [RREL,M,128]
                          int M, int do_relu) {
    extern __shared__ float smem[];
    float* As = smem;                      // [128][AS_STRIDE]
    float* Bs = smem + 128 * AS_STRIDE;    // [128][BS_STRIDE]

    const int tid = threadIdx.x;
    const int row0 = blockIdx.x * 128;
    const int r = blockIdx.y;

    // --- load A tile (relu optional) and W_r tile ---
    {
        const int ar = tid >> 1;
        const int ac = (tid & 1) * 64;
        const int gm = row0 + ar;
        #pragma unroll
        for (int i = 0; i < 16; i++) {
            float4 v = make_float4(0.f, 0.f, 0.f, 0.f);
            if (gm < M)
                v = __ldg((const float4*)(A + (size_t)gm * 128 + ac) + i);
            if (do_relu) {
                v.x = fmaxf(v.x, 0.f); v.y = fmaxf(v.y, 0.f);
                v.z = fmaxf(v.z, 0.f); v.w = fmaxf(v.w, 0.f);
            }
            *(float4*)&As[ar * AS_STRIDE + ac + i * 4] = v;
        }
        const float* Wr = W + (size_t)r * 128 * 128;
        #pragma unroll
        for (int i = 0; i < 16; i++) {
            float4 v = __ldg((const float4*)(Wr + (size_t)ar * 128 + ac) + i);
            *(float4*)&Bs[ar * BS_STRIDE + ac + i * 4] = v;
        }
    }
    __syncthreads();

    const int lane = tid & 31;
    const int g = lane >> 2;     // groupID
    const int tg = lane & 3;     // thread-in-group
    const int wid = tid >> 5;
    const int wm = (wid & 3) * 32;
    const int wn = (wid >> 2) * 64;

    float acc[2][8][4];
    #pragma unroll
    for (int mt = 0; mt < 2; mt++)
        #pragma unroll
        for (int nt = 0; nt < 8; nt++)
            #pragma unroll
            for (int q = 0; q < 4; q++) acc[mt][nt][q] = 0.f;

    #pragma unroll
    for (int ks = 0; ks < 16; ks++) {
        const int k0 = ks * 8;
        // A fragments (hi/lo) for 2 m-tiles
        uint32_t ahi[2][4], alo[2][4];
        #pragma unroll
        for (int mt = 0; mt < 2; mt++) {
            const int m = wm + mt * 16;
            float v0 = As[(m + g)     * AS_STRIDE + k0 + tg];
            float v1 = As[(m + g + 8) * AS_STRIDE + k0 + tg];
            float v2 = As[(m + g)     * AS_STRIDE + k0 + tg + 4];
            float v3 = As[(m + g + 8) * AS_STRIDE + k0 + tg + 4];
            split_tf32(v0, ahi[mt][0], alo[mt][0]);
            split_tf32(v1, ahi[mt][1], alo[mt][1]);
            split_tf32(v2, ahi[mt][2], alo[mt][2]);
            split_tf32(v3, ahi[mt][3], alo[mt][3]);
        }
        #pragma unroll
        for (int nt = 0; nt < 8; nt++) {
            const int n = wn + nt * 8 + g;
            float w0 = Bs[(k0 + tg)     * BS_STRIDE + n];
            float w1 = Bs[(k0 + tg + 4) * BS_STRIDE + n];
            uint32_t bh0, bl0, bh1, bl1;
            split_tf32(w0, bh0, bl0);
            split_tf32(w1, bh1, bl1);
            #pragma unroll
            for (int mt = 0; mt < 2; mt++) {
                mma_tf32(acc[mt][nt], ahi[mt], bh0, bh1);
                mma_tf32(acc[mt][nt], ahi[mt], bl0, bl1);
                mma_tf32(acc[mt][nt], alo[mt], bh0, bh1);
            }
        }
    }

    // --- store Y ---
    float* Yr = Y + (size_t)r * M * 128;
    #pragma unroll
    for (int mt = 0; mt < 2; mt++) {
        const int rlo = row0 + wm + mt * 16 + g;
        const int rhi = rlo + 8;
        #pragma unroll
        for (int nt = 0; nt < 8; nt++) {
            const int col = wn + nt * 8 + tg * 2;
            if (rlo < M)
                *(float2*)(Yr + (size_t)rlo * 128 + col) =
                    make_float2(acc[mt][nt][0], acc[mt][nt][1]);
            if (rhi < M)
                *(float2*)(Yr + (size_t)rhi * 128 + col) =
                    make_float2(acc[mt][nt][2], acc[mt][nt][3]);
        }
    }
}

// ---------------------------------------------------------------------------
// DDI edge scatter: h[dst] += c * y[r][src];  c = rn_out[r][src]*rn_in[r][dst]
// 32 edges per warp, coalesced index staging + shfl broadcast.
// ---------------------------------------------------------------------------
__global__ void scatter_ddi_kernel(const float* __restrict__ y,
                                   float* __restrict__ h,
                                   const int* __restrict__ src,
                                   const int* __restrict__ dst) {
    const int r = blockIdx.y;
    const int lane = threadIdx.x & 31;
    const int warp = blockIdx.x * (blockDim.x >> 5) + (threadIdx.x >> 5);
    const int e0 = warp * 32;
    if (e0 >= E_DDI) return;
    const int n = (E_DDI - e0 < 32) ? (E_DDI - e0) : 32;

    int soff = 0, doff = 0;
    float c = 0.0f;
    if (lane < n) {
        int e = e0 + lane;
        int s = __ldg(src + (size_t)r * E_DDI + e);
        int d = __ldg(dst + (size_t)r * E_DDI + e);
        c = __ldg(g_deg + OFF_OUT_DDI + r * ND + s) *
            __ldg(g_deg + OFF_IN_DDI  + r * ND + d);
        soff = s * 32;     // float4 units within y[r]
        doff = d * 32;     // float4 units within h
    }

    const float4* __restrict__ yv = (const float4*)(y + (size_t)r * ND * 128);
    float4* hv = (float4*)h;

    if (n == 32) {
        #pragma unroll 4
        for (int j = 0; j < 32; j++) {
            int sj   = __shfl_sync(0xffffffffu, soff, j);
            int dj   = __shfl_sync(0xffffffffu, doff, j);
            float cj = __shfl_sync(0xffffffffu, c, j);
            float4 v = __ldg(yv + sj + lane);
            v.x *= cj; v.y *= cj; v.z *= cj; v.w *= cj;
            red_add_v4(hv + dj + lane, v);
        }
    } else {
        for (int j = 0; j < n; j++) {
            int sj   = __shfl_sync(0xffffffffu, soff, j);
            int dj   = __shfl_sync(0xffffffffu, doff, j);
            float cj = __shfl_sync(0xffffffffu, c, j);
            float4 v = __ldg(yv + sj + lane);
            v.x *= cj; v.y *= cj; v.z *= cj; v.w *= cj;
            red_add_v4(hv + dj + lane, v);
        }
    }
}

// PDI scatter: h1[dst] += hp[src] * rn_in_pdi[dst]  (src norm folded into GEMM)
__global__ void scatter_pdi_kernel(const int* __restrict__ src,
                                   const int* __restrict__ dst) {
    const int lane = threadIdx.x & 31;
    const int warp = blockIdx.x * (blockDim.x >> 5) + (threadIdx.x >> 5);
    const int e0 = warp * 32;
    if (e0 >= E_PDI) return;
    const int n = (E_PDI - e0 < 32) ? (E_PDI - e0) : 32;

    int soff = 0, doff = 0;
    float c = 0.0f;
    if (lane < n) {
        int e = e0 + lane;
        int s = __ldg(src + e);
        int d = __ldg(dst + e);
        c = __ldg(g_deg + OFF_IN_PDI + d);
        soff = s * 32;
        doff = d * 32;
    }

    const float4* __restrict__ hpv = (const float4*)g_hp;
    float4* h1v = (float4*)g_h1;

    #pragma unroll 4
    for (int j = 0; j < 32; j++) {
        if (j >= n) break;
        int sj   = __shfl_sync(0xffffffffu, soff, j);
        int dj   = __shfl_sync(0xffffffffu, doff, j);
        float cj = __shfl_sync(0xffffffffu, c, j);
        float4 v = __ldg(hpv + sj + lane);
        v.x *= cj; v.y *= cj; v.z *= cj; v.w *= cj;
        red_add_v4(h1v + dj + lane, v);
    }
}

// ---------------------------------------------------------------------------
// FFMA SGEMM (kept for the PDI branch, K=256):
// C[M,128] = A[M,K] @ B[K,128], optional per-row scale on A.
// ---------------------------------------------------------------------------
#define BM 128
#define BN 128
#define BK 16

__global__ __launch_bounds__(256, 2)
void gemm128_kernel(const float* __restrict__ A, const float* __restrict__ B,
                    float* __restrict__ C, int M, int K,
                    const float* __restrict__ row_scale) {
    __shared__ float As[2][BK][BM + 4];
    __shared__ float Bs[2][BK][BN];

    const int tid = threadIdx.x;
    const int tx = tid & 15;
    const int ty = tid >> 4;
    const int a_r = tid >> 2;
    const int a_c = (tid & 3) << 2;
    const int b_r = tid >> 5;
    const int b_c = (tid & 31) << 2;
    const int row0 = blockIdx.x * BM;

    float rs0 = 1.0f, rs1 = 1.0f;
    const int gm0 = row0 + a_r;
    const int gm1 = row0 + a_r + 64;
    if (row_scale) {
        if (gm0 < M) rs0 = __ldg(row_scale + gm0);
        if (gm1 < M) rs1 = __ldg(row_scale + gm1);
    }

    float acc[8][8];
    #pragma unroll
    for (int i = 0; i < 8; i++)
        #pragma unroll
        for (int j = 0; j < 8; j++) acc[i][j] = 0.0f;

    float4 pa0, pa1, pb0, pb1;

    pa0 = make_float4(0.f,0.f,0.f,0.f);
    pa1 = make_float4(0.f,0.f,0.f,0.f);
    if (gm0 < M) pa0 = __ldg((const float4*)(A + (size_t)gm0 * K + a_c));
    if (gm1 < M) pa1 = __ldg((const float4*)(A + (size_t)gm1 * K + a_c));
    pb0 = __ldg((const float4*)(B + (size_t)b_r * BN + b_c));
    pb1 = __ldg((const float4*)(B + (size_t)(b_r + 8) * BN + b_c));

    As[0][a_c + 0][a_r] = pa0.x * rs0;
    As[0][a_c + 1][a_r] = pa0.y * rs0;
    As[0][a_c + 2][a_r] = pa0.z * rs0;
    As[0][a_c + 3][a_r] = pa0.w * rs0;
    As[0][a_c + 0][a_r + 64] = pa1.x * rs1;
    As[0][a_c + 1][a_r + 64] = pa1.y * rs1;
    As[0][a_c + 2][a_r + 64] = pa1.z * rs1;
    As[0][a_c + 3][a_r + 64] = pa1.w * rs1;
    *(float4*)&Bs[0][b_r][b_c]     = pb0;
    *(float4*)&Bs[0][b_r + 8][b_c] = pb1;
    __syncthreads();

    const int ntiles = K / BK;
    int buf = 0;

    for (int t = 0; t < ntiles; t++) {
        const int k0n = (t + 1) * BK;
        if (t + 1 < ntiles) {
            pa0 = make_float4(0.f,0.f,0.f,0.f);
            pa1 = make_float4(0.f,0.f,0.f,0.f);
            if (gm0 < M) pa0 = __ldg((const float4*)(A + (size_t)gm0 * K + k0n + a_c));
            if (gm1 < M) pa1 = __ldg((const float4*)(A + (size_t)gm1 * K + k0n + a_c));
            pb0 = __ldg((const float4*)(B + (size_t)(k0n + b_r) * BN + b_c));
            pb1 = __ldg((const float4*)(B + (size_t)(k0n + b_r + 8) * BN + b_c));
        }

        #pragma unroll
        for (int k = 0; k < BK; k++) {
            float4 a0 = *(const float4*)&As[buf][k][ty * 8];
            float4 a1 = *(const float4*)&As[buf][k][ty * 8 + 4];
            float4 b0 = *(const float4*)&Bs[buf][k][tx * 8];
            float4 b1 = *(const float4*)&Bs[buf][k][tx * 8 + 4];
            float ra[8] = {a0.x, a0.y, a0.z, a0.w, a1.x, a1.y, a1.z, a1.w};
            float rb[8] = {b0.x, b0.y, b0.z, b0.w, b1.x, b1.y, b1.z, b1.w};
            #pragma unroll
            for (int i = 0; i < 8; i++)
                #pragma unroll
                for (int j = 0; j < 8; j++)
                    acc[i][j] = fmaf(ra[i], rb[j], acc[i][j]);
        }

        if (t + 1 < ntiles) {
            int nb = buf ^ 1;
            As[nb][a_c + 0][a_r] = pa0.x * rs0;
            As[nb][a_c + 1][a_r] = pa0.y * rs0;
            As[nb][a_c + 2][a_r] = pa0.z * rs0;
            As[nb][a_c + 3][a_r] = pa0.w * rs0;
            As[nb][a_c + 0][a_r + 64] = pa1.x * rs1;
            As[nb][a_c + 1][a_r + 64] = pa1.y * rs1;
            As[nb][a_c + 2][a_r + 64] = pa1.z * rs1;
            As[nb][a_c + 3][a_r + 64] = pa1.w * rs1;
            *(float4*)&Bs[nb][b_r][b_c]     = pb0;
            *(float4*)&Bs[nb][b_r + 8][b_c] = pb1;
            __syncthreads();
            buf = nb;
        }
    }

    #pragma unroll
    for (int i = 0; i < 8; i++) {
        int gm = row0 + ty * 8 + i;
        if (gm >= M) continue;
        float* cp = C + (size_t)gm * BN + tx * 8;
        *(float4*)(cp)     = make_float4(acc[i][0], acc[i][1], acc[i][2], acc[i][3]);
        *(float4*)(cp + 4) = make_float4(acc[i][4], acc[i][5], acc[i][6], acc[i][7]);
    }
}

// ---------------------------------------------------------------------------
// Launch
// ---------------------------------------------------------------------------
extern "C" void kernel_launch(void* const* d_in, const int* in_sizes, int n_in,
                              void* d_out, int out_size) {
    const float* x_d    = (const float*)d_in[0];
    const float* x_p    = (const float*)d_in[1];
    const float* W1     = (const float*)d_in[2];   // [4,128,128]
    const float* b1     = (const float*)d_in[3];   // [4,128]
    const float* W1_pdi = (const float*)d_in[4];   // [256,128]
    const float* b1_pdi = (const float*)d_in[5];   // [128]
    // d_in[6], d_in[7]: W1_ppi / b1_ppi -- dead code, unused
    const float* W2     = (const float*)d_in[8];
    const float* b2     = (const float*)d_in[9];
    const float* W3     = (const float*)d_in[10];
    const float* b3     = (const float*)d_in[11];
    const int* ddi_src  = (const int*)d_in[12];
    const int* ddi_dst  = (const int*)d_in[13];
    const int* pdi_src  = (const int*)d_in[14];
    const int* pdi_dst  = (const int*)d_in[15];
    // d_in[16], d_in[17]: ppi edges -- dead code, unused
    float* out = (float*)d_out;

    float *y, *h1, *h2, *hp, *deg;
    cudaGetSymbolAddress((void**)&y, g_y);
    cudaGetSymbolAddress((void**)&h1, g_h1);
    cudaGetSymbolAddress((void**)&h2, g_h2);
    cudaGetSymbolAddress((void**)&hp, g_hp);
    cudaGetSymbolAddress((void**)&deg, g_deg);

    cudaFuncSetAttribute(gemm_tf32_rel_kernel,
                         cudaFuncAttributeMaxDynamicSharedMemorySize, GEMM_SMEM);

    const float* rn_out_pdi = deg + OFF_OUT_PDI;

    const dim3 GEMM_TC((ND + 127) / 128, RREL);       // (313, 4)
    const int GEMM_BLOCKS_P = (NP + BM - 1) / BM;     // 157
    const int SCAT_BLKS = (E_DDI + 255) / 256;        // 32 edges/warp, 8 warps/blk
    const dim3 SCAT_DDI(SCAT_BLKS, RREL);
    const dim3 CNT_DDI((E_DDI + 255) / 256, RREL);
    const int BIAS_BLKS = (ND * 32 + 255) / 256;

    // --- degrees ---
    cudaMemsetAsync(deg, 0, (size_t)DEG_TOTAL * sizeof(float));
    count_ddi_kernel<<<CNT_DDI, 256>>>(ddi_src, ddi_dst);
    count_pdi_kernel<<<(E_PDI + 255) / 256, 256>>>(pdi_src, pdi_dst);
    finalize_deg_kernel<<<(DEG_TOTAL + 255) / 256, 256>>>();

    // --- Layer 1 ---
    gemm_tf32_rel_kernel<<<GEMM_TC, 256, GEMM_SMEM>>>(x_d, W1, y, ND, 0);
    gemm128_kernel<<<GEMM_BLOCKS_P, 256>>>(x_p, W1_pdi, hp, NP, FP, rn_out_pdi);
    bias_init_kernel<<<BIAS_BLKS, 256>>>(h1, b1, RREL, b1_pdi, ND);
    scatter_pdi_kernel<<<(E_PDI + 255) / 256, 256>>>(pdi_src, pdi_dst);
    scatter_ddi_kernel<<<SCAT_DDI, 256>>>(y, h1, ddi_src, ddi_dst);

    // --- Layer 2 ---  (relu of h1 folded into GEMM A-load)
    gemm_tf32_rel_kernel<<<GEMM_TC, 256, GEMM_SMEM>>>(h1, W2, y, ND, 1);
    bias_init_kernel<<<BIAS_BLKS, 256>>>(h2, b2, RREL, nullptr, ND);
    scatter_ddi_kernel<<<SCAT_DDI, 256>>>(y, h2, ddi_src, ddi_dst);

    // --- Layer 3 ---
    gemm_tf32_rel_kernel<<<GEMM_TC, 256, GEMM_SMEM>>>(h2, W3, y, ND, 1);
    bias_init_kernel<<<BIAS_BLKS, 256>>>(out, b3, RREL, nullptr, ND);
    scatter_ddi_kernel<<<SCAT_DDI, 256>>>(y, out, ddi_src, ddi_dst);
}